// round 6
// baseline (speedup 1.0000x reference)
#include <cuda_runtime.h>
#include <cuda_bf16.h>
#include <cstdint>

// CartesianToDihedral: (1024, 2048, 3, 3) f32 -> (angles (1024,12282), first_three (1024,9))
// Smem-staged input tile (coalesced LDG.128 -> conflict-free LDS.128),
// W=4 windows/thread, third cross eliminated: yc = (n1 x u).n2 == -e0.n2.

namespace {
constexpr int B_SZ        = 1024;
constexpr int PTS_PER_ROW = 6144;                 // 2048*3
constexpr int FLT_PER_ROW = PTS_PER_ROW * 3;      // 18432
constexpr int NWIN        = PTS_PER_ROW - 3;      // 6141
constexpr int OUT_STRIDE  = 2 * NWIN;             // 12282
constexpr int W           = 4;                    // windows per thread
constexpr int TPB         = 256;
constexpr int WIN_PER_BLK = W * TPB;              // 1024
constexpr int CHUNKS      = 6;                    // 6*1024 = 6144 >= 6141
constexpr int TILE_FLTS   = WIN_PER_BLK * 3 + 9;  // 3081
constexpr int TILE_PAD    = 3084;                 // pad to float4 multiple
constexpr int TILE_V4     = TILE_PAD / 4;         // 771
constexpr long long TOTAL_IN = (long long)B_SZ * FLT_PER_ROW;  // 18,874,368
}

__device__ __forceinline__ void dihedral_core(
    const float* e0, const float* e1, const float* e2,
    float& sv, float& cv)
{
    // u = normalize(e1 + 1e-8)
    const float ux0 = e1[0] + 1e-8f;
    const float uy0 = e1[1] + 1e-8f;
    const float uz0 = e1[2] + 1e-8f;
    const float rin = rsqrtf(fmaf(ux0, ux0, fmaf(uy0, uy0, uz0 * uz0)));
    const float ux = ux0 * rin, uy = uy0 * rin, uz = uz0 * rin;

    // n1 = cross(e0, u)
    const float n1x = fmaf(e0[1], uz, -e0[2] * uy);
    const float n1y = fmaf(e0[2], ux, -e0[0] * uz);
    const float n1z = fmaf(e0[0], uy, -e0[1] * ux);
    // n2 = cross(u, e2)
    const float n2x = fmaf(uy, e2[2], -uz * e2[1]);
    const float n2y = fmaf(uz, e2[0], -ux * e2[2]);
    const float n2z = fmaf(ux, e2[1], -uy * e2[0]);

    // xc = n1.n2 + 1e-8 ; yc = (n1 x u).n2 == -e0.n2  (u.n2 == 0, |u| = 1)
    const float xc = fmaf(n1x, n2x, fmaf(n1y, n2y, fmaf(n1z, n2z, 1e-8f)));
    const float yc = -fmaf(e0[0], n2x, fmaf(e0[1], n2y, e0[2] * n2z));

    const float r2 = fmaf(xc, xc, yc * yc);
    const float ri = rsqrtf(r2);
    sv = (r2 > 0.0f) ? yc * ri : 0.0f;   // atan2(0,0)=0
    cv = (r2 > 0.0f) ? xc * ri : 1.0f;
}

__global__ __launch_bounds__(TPB)
void dihedral_kernel(const float* __restrict__ in, float* __restrict__ out) {
    __shared__ float s[TILE_PAD];

    const int bid   = blockIdx.x;
    const int batch = bid / CHUNKS;
    const int chunk = bid - batch * CHUNKS;
    const int w0    = chunk * WIN_PER_BLK;                    // block's first window

    const long long rowBase  = (long long)batch * FLT_PER_ROW;
    const long long tileBase = rowBase + (long long)w0 * 3;   // w0*3 = chunk*3072, mult of 4

    // ── Coalesced tile load: 771 float4s per block, consecutive per lane ──
    float4* s4 = reinterpret_cast<float4*>(s);
    const float4* in4 = reinterpret_cast<const float4*>(in + tileBase);
    #pragma unroll
    for (int t = threadIdx.x; t < TILE_V4; t += TPB) {
        const long long gf = tileBase + (long long)t * 4;
        float4 v;
        if (gf + 4 <= TOTAL_IN) {
            v = in4[t];
        } else {                       // only the last block's tail float4s
            v = make_float4(0.f, 0.f, 0.f, 0.f);
            if (gf + 0 < TOTAL_IN) v.x = in[gf + 0];
            if (gf + 1 < TOTAL_IN) v.y = in[gf + 1];
            if (gf + 2 < TOTAL_IN) v.z = in[gf + 2];
        }
        s4[t] = v;
    }
    __syncthreads();

    // ── Per-thread: 24 floats via 6 conflict-free LDS.128 (48B/lane stride) ──
    float f[24];
    {
        const float4* p4 = reinterpret_cast<const float4*>(s + threadIdx.x * 12);
        #pragma unroll
        for (int t = 0; t < 6; t++) {
            const float4 v = p4[t];
            f[4*t+0] = v.x; f[4*t+1] = v.y; f[4*t+2] = v.z; f[4*t+3] = v.w;
        }
    }

    // Edges e_j = p_j - p_{j+1}, j = 0..5
    float e[W + 2][3];
    #pragma unroll
    for (int j = 0; j < W + 2; j++) {
        e[j][0] = f[3*j+0] - f[3*j+3];
        e[j][1] = f[3*j+1] - f[3*j+4];
        e[j][2] = f[3*j+2] - f[3*j+5];
    }

    float sv[W], cv[W];
    #pragma unroll
    for (int w = 0; w < W; w++)
        dihedral_core(e[w], e[w+1], e[w+2], sv[w], cv[w]);

    const int gw0 = w0 + threadIdx.x * W;
    const long long ob = (long long)batch * OUT_STRIDE;

    if (gw0 + W <= NWIN) {
        // sin: (ob+gw0) even -> 8B-aligned float2 stores
        float2* s2 = reinterpret_cast<float2*>(out + ob + gw0);
        s2[0] = make_float2(sv[0], sv[1]);
        s2[1] = make_float2(sv[2], sv[3]);
        // cos: offset NWIN (odd) -> scalar stores
        float* cp = out + ob + NWIN + gw0;
        cp[0] = cv[0]; cp[1] = cv[1]; cp[2] = cv[2]; cp[3] = cv[3];
    } else {
        #pragma unroll
        for (int w = 0; w < W; w++) {
            if (gw0 + w < NWIN) {
                out[ob + gw0 + w]        = sv[w];
                out[ob + NWIN + gw0 + w] = cv[w];
            }
        }
    }

    // first_three: 9 floats per batch appended after all angle rows.
    if (chunk == 0 && threadIdx.x < 9) {
        out[(long long)B_SZ * OUT_STRIDE + (long long)batch * 9 + threadIdx.x] =
            in[rowBase + threadIdx.x];
    }
}

extern "C" void kernel_launch(void* const* d_in, const int* in_sizes, int n_in,
                              void* d_out, int out_size) {
    const float* in = (const float*)d_in[0];
    float* out = (float*)d_out;
    dihedral_kernel<<<B_SZ * CHUNKS, TPB>>>(in, out);
}

// round 8
// speedup vs baseline: 1.2157x; 1.2157x over previous
#include <cuda_runtime.h>
#include <cuda_bf16.h>
#include <cstdint>

// CartesianToDihedral: (1024, 2048, 3, 3) f32 -> (angles (1024,12282), first_three (1024,9))
// W=2 windows/thread: 8x LDG.64 (24B lane stride -> 6 lines/instr),
// coalesced STG.64 sin stores, streaming (__stcs) output stores,
// third cross eliminated: yc = (n1 x u).n2 == -e0.n2.

namespace {
constexpr int B_SZ        = 1024;
constexpr int PTS_PER_ROW = 6144;                 // 2048*3
constexpr int FLT_PER_ROW = PTS_PER_ROW * 3;      // 18432
constexpr int NWIN        = PTS_PER_ROW - 3;      // 6141
constexpr int OUT_STRIDE  = 2 * NWIN;             // 12282
constexpr int W           = 2;                    // windows per thread
constexpr int TPB         = 256;
constexpr int WIN_PER_BLK = W * TPB;              // 512
constexpr int CHUNKS      = 12;                   // 12*512 = 6144 >= 6141
constexpr long long TOTAL_IN = (long long)B_SZ * FLT_PER_ROW;  // 18,874,368
}

__device__ __forceinline__ void dihedral_core(
    const float* e0, const float* e1, const float* e2,
    float& sv, float& cv)
{
    // u = normalize(e1 + 1e-8)
    const float ux0 = e1[0] + 1e-8f;
    const float uy0 = e1[1] + 1e-8f;
    const float uz0 = e1[2] + 1e-8f;
    const float rin = rsqrtf(fmaf(ux0, ux0, fmaf(uy0, uy0, uz0 * uz0)));
    const float ux = ux0 * rin, uy = uy0 * rin, uz = uz0 * rin;

    // n1 = cross(e0, u)
    const float n1x = fmaf(e0[1], uz, -e0[2] * uy);
    const float n1y = fmaf(e0[2], ux, -e0[0] * uz);
    const float n1z = fmaf(e0[0], uy, -e0[1] * ux);
    // n2 = cross(u, e2)
    const float n2x = fmaf(uy, e2[2], -uz * e2[1]);
    const float n2y = fmaf(uz, e2[0], -ux * e2[2]);
    const float n2z = fmaf(ux, e2[1], -uy * e2[0]);

    // xc = n1.n2 + 1e-8 ; yc = (n1 x u).n2 == -e0.n2  (u.n2 == 0, |u| = 1)
    const float xc = fmaf(n1x, n2x, fmaf(n1y, n2y, fmaf(n1z, n2z, 1e-8f)));
    const float yc = -fmaf(e0[0], n2x, fmaf(e0[1], n2y, e0[2] * n2z));

    const float r2 = fmaf(xc, xc, yc * yc);
    const float ri = rsqrtf(r2);
    sv = (r2 > 0.0f) ? yc * ri : 0.0f;   // atan2(0,0)=0
    cv = (r2 > 0.0f) ? xc * ri : 1.0f;
}

__global__ __launch_bounds__(TPB)
void dihedral_kernel(const float* __restrict__ in, float* __restrict__ out) {
    const int bid   = blockIdx.x;
    const int batch = bid / CHUNKS;
    const int chunk = bid - batch * CHUNKS;
    const int gw0   = chunk * WIN_PER_BLK + threadIdx.x * W;  // even

    const long long rowBase = (long long)batch * FLT_PER_ROW;
    const long long fbase   = rowBase + (long long)gw0 * 3;   // multiple of 2 -> 8B aligned

    // 5 points = 15 floats (16 with pad) via 8 aligned LDG.64 (24B lane stride).
    float f[16];
    if (fbase + 16 <= TOTAL_IN) {
        const float2* p2 = reinterpret_cast<const float2*>(in + fbase);
        #pragma unroll
        for (int t = 0; t < 8; t++) {
            const float2 v = p2[t];
            f[2*t+0] = v.x; f[2*t+1] = v.y;
        }
    } else {                                   // only near the global tail
        #pragma unroll
        for (int t = 0; t < 16; t++)
            f[t] = (fbase + t < TOTAL_IN) ? in[fbase + t] : 0.0f;
    }

    // Edges e_j = p_j - p_{j+1}, j = 0..3
    float e[W + 2][3];
    #pragma unroll
    for (int j = 0; j < W + 2; j++) {
        e[j][0] = f[3*j+0] - f[3*j+3];
        e[j][1] = f[3*j+1] - f[3*j+4];
        e[j][2] = f[3*j+2] - f[3*j+5];
    }

    float sv[W], cv[W];
    #pragma unroll
    for (int w = 0; w < W; w++)
        dihedral_core(e[w], e[w+1], e[w+2], sv[w], cv[w]);

    const long long ob = (long long)batch * OUT_STRIDE;

    if (gw0 + W <= NWIN) {
        // sin: contiguous across the warp -> one coalesced STG.64, streaming
        __stcs(reinterpret_cast<float2*>(out + ob + gw0), make_float2(sv[0], sv[1]));
        // cos: offset NWIN (odd) -> two streaming scalar stores (8B lane stride)
        __stcs(out + ob + NWIN + gw0 + 0, cv[0]);
        __stcs(out + ob + NWIN + gw0 + 1, cv[1]);
    } else {
        #pragma unroll
        for (int w = 0; w < W; w++) {
            if (gw0 + w < NWIN) {
                __stcs(out + ob + gw0 + w,        sv[w]);
                __stcs(out + ob + NWIN + gw0 + w, cv[w]);
            }
        }
    }

    // first_three: 9 floats per batch appended after all angle rows.
    if (chunk == 0 && threadIdx.x < 9) {
        out[(long long)B_SZ * OUT_STRIDE + (long long)batch * 9 + threadIdx.x] =
            in[rowBase + threadIdx.x];
    }
}

extern "C" void kernel_launch(void* const* d_in, const int* in_sizes, int n_in,
                              void* d_out, int out_size) {
    const float* in = (const float*)d_in[0];
    float* out = (float*)d_out;
    dihedral_kernel<<<B_SZ * CHUNKS, TPB>>>(in, out);
}

// round 9
// speedup vs baseline: 1.3542x; 1.1139x over previous
#include <cuda_runtime.h>
#include <cuda_bf16.h>
#include <cstdint>

// CartesianToDihedral: (1024, 2048, 3, 3) f32 -> (angles (1024,12282), first_three (1024,9))
// W=4 windows/thread. Each thread loads ONLY its 12 owned floats (3x LDG.128,
// 48B lane stride = 12 lines/instr); the 9-float overlap comes from lane+1 via
// __shfl_down (lane 31 direct-loads). Third cross eliminated: yc = -e0.n2.

namespace {
constexpr int B_SZ        = 1024;
constexpr int PTS_PER_ROW = 6144;                 // 2048*3
constexpr int FLT_PER_ROW = PTS_PER_ROW * 3;      // 18432
constexpr int NWIN        = PTS_PER_ROW - 3;      // 6141
constexpr int OUT_STRIDE  = 2 * NWIN;             // 12282
constexpr int W           = 4;                    // windows per thread
constexpr int TPB         = 256;
constexpr int WIN_PER_BLK = W * TPB;              // 1024
constexpr int CHUNKS      = 6;                    // 6*1024 = 6144 >= 6141
constexpr long long TOTAL_IN = (long long)B_SZ * FLT_PER_ROW;  // 18,874,368
}

__device__ __forceinline__ void dihedral_core(
    const float* e0, const float* e1, const float* e2,
    float& sv, float& cv)
{
    // u = normalize(e1 + 1e-8)
    const float ux0 = e1[0] + 1e-8f;
    const float uy0 = e1[1] + 1e-8f;
    const float uz0 = e1[2] + 1e-8f;
    const float rin = rsqrtf(fmaf(ux0, ux0, fmaf(uy0, uy0, uz0 * uz0)));
    const float ux = ux0 * rin, uy = uy0 * rin, uz = uz0 * rin;

    // n1 = cross(e0, u)
    const float n1x = fmaf(e0[1], uz, -e0[2] * uy);
    const float n1y = fmaf(e0[2], ux, -e0[0] * uz);
    const float n1z = fmaf(e0[0], uy, -e0[1] * ux);
    // n2 = cross(u, e2)
    const float n2x = fmaf(uy, e2[2], -uz * e2[1]);
    const float n2y = fmaf(uz, e2[0], -ux * e2[2]);
    const float n2z = fmaf(ux, e2[1], -uy * e2[0]);

    // xc = n1.n2 + 1e-8 ; yc = (n1 x u).n2 == -e0.n2  (u.n2 == 0, |u| = 1)
    const float xc = fmaf(n1x, n2x, fmaf(n1y, n2y, fmaf(n1z, n2z, 1e-8f)));
    const float yc = -fmaf(e0[0], n2x, fmaf(e0[1], n2y, e0[2] * n2z));

    const float r2 = fmaf(xc, xc, yc * yc);
    const float ri = rsqrtf(r2);
    sv = (r2 > 0.0f) ? yc * ri : 0.0f;   // atan2(0,0)=0
    cv = (r2 > 0.0f) ? xc * ri : 1.0f;
}

__global__ __launch_bounds__(TPB)
void dihedral_kernel(const float* __restrict__ in, float* __restrict__ out) {
    const int bid   = blockIdx.x;
    const int batch = bid / CHUNKS;
    const int chunk = bid - batch * CHUNKS;
    const int lane  = threadIdx.x & 31;
    const int gw0   = chunk * WIN_PER_BLK + threadIdx.x * W;

    const long long rowBase = (long long)batch * FLT_PER_ROW;
    const long long fbase   = rowBase + (long long)gw0 * 3;   // multiple of 12 -> 16B aligned

    // ── Owned floats: f[0..11] via 3 aligned LDG.128 (48B lane stride, 12 lines/instr).
    // Always in bounds: max fbase+12 == TOTAL_IN exactly.
    float f[12];
    {
        const float4* p4 = reinterpret_cast<const float4*>(in + fbase);
        #pragma unroll
        for (int t = 0; t < 3; t++) {
            const float4 v = p4[t];
            f[4*t+0] = v.x; f[4*t+1] = v.y; f[4*t+2] = v.z; f[4*t+3] = v.w;
        }
    }

    // ── Overlap floats g[0..8] = next thread's f[0..8], via shuffle-down.
    float g[9];
    #pragma unroll
    for (int j = 0; j < 9; j++)
        g[j] = __shfl_down_sync(0xFFFFFFFFu, f[j], 1);

    if (lane == 31) {  // next thread is in another warp -> direct load
        const long long gbase = fbase + 12;      // 16B aligned
        if (gbase + 9 <= TOTAL_IN) {             // always true except global tail thread
            const float4 v0 = *reinterpret_cast<const float4*>(in + gbase);
            const float4 v1 = *reinterpret_cast<const float4*>(in + gbase + 4);
            g[0] = v0.x; g[1] = v0.y; g[2] = v0.z; g[3] = v0.w;
            g[4] = v1.x; g[5] = v1.y; g[6] = v1.z; g[7] = v1.w;
            g[8] = in[gbase + 8];
        } else {
            #pragma unroll
            for (int j = 0; j < 9; j++)
                g[j] = (gbase + j < TOTAL_IN) ? in[gbase + j] : 0.0f;
        }
    }

    // Edges e_j = p_j - p_{j+1} over the 21 floats [f | g].
    float e[W + 2][3];
    #pragma unroll
    for (int j = 0; j < W + 2; j++) {
        #pragma unroll
        for (int k = 0; k < 3; k++) {
            const int i0 = 3*j + k, i1 = 3*j + 3 + k;
            const float a = (i0 < 12) ? f[i0] : g[i0 - 12];
            const float b = (i1 < 12) ? f[i1] : g[i1 - 12];
            e[j][k] = a - b;
        }
    }

    float sv[W], cv[W];
    #pragma unroll
    for (int w = 0; w < W; w++)
        dihedral_core(e[w], e[w+1], e[w+2], sv[w], cv[w]);

    const long long ob = (long long)batch * OUT_STRIDE;

    if (gw0 + W <= NWIN) {
        // sin: (ob+gw0) even -> 8B-aligned float2 stores
        float2* s2 = reinterpret_cast<float2*>(out + ob + gw0);
        s2[0] = make_float2(sv[0], sv[1]);
        s2[1] = make_float2(sv[2], sv[3]);
        // cos: offset NWIN (odd) -> scalar stores (warp-contiguous)
        float* cp = out + ob + NWIN + gw0;
        cp[0] = cv[0]; cp[1] = cv[1]; cp[2] = cv[2]; cp[3] = cv[3];
    } else {
        #pragma unroll
        for (int w = 0; w < W; w++) {
            if (gw0 + w < NWIN) {
                out[ob + gw0 + w]        = sv[w];
                out[ob + NWIN + gw0 + w] = cv[w];
            }
        }
    }

    // first_three: 9 floats per batch appended after all angle rows.
    if (chunk == 0 && threadIdx.x < 9) {
        out[(long long)B_SZ * OUT_STRIDE + (long long)batch * 9 + threadIdx.x] =
            in[rowBase + threadIdx.x];
    }
}

extern "C" void kernel_launch(void* const* d_in, const int* in_sizes, int n_in,
                              void* d_out, int out_size) {
    const float* in = (const float*)d_in[0];
    float* out = (float*)d_out;
    dihedral_kernel<<<B_SZ * CHUNKS, TPB>>>(in, out);
}

// round 10
// speedup vs baseline: 1.3791x; 1.0184x over previous
#include <cuda_runtime.h>
#include <cuda_bf16.h>
#include <cstdint>

// CartesianToDihedral: (1024, 2048, 3, 3) f32 -> (angles (1024,12282), first_three (1024,9))
// W=4 windows/thread. Thread loads only its 12 owned floats (3x LDG.128);
// overlap comes from lane+1 via shuffles of EDGES (E4=E0', E5=E1') + p4.
// Lane-31 overlap loads hoisted for MLP. Streaming (__stcs) output stores.
// Third cross eliminated: yc = (n1 x u).n2 == -e0.n2.

namespace {
constexpr int B_SZ        = 1024;
constexpr int PTS_PER_ROW = 6144;                 // 2048*3
constexpr int FLT_PER_ROW = PTS_PER_ROW * 3;      // 18432
constexpr int NWIN        = PTS_PER_ROW - 3;      // 6141
constexpr int OUT_STRIDE  = 2 * NWIN;             // 12282
constexpr int W           = 4;                    // windows per thread
constexpr int TPB         = 256;
constexpr int WIN_PER_BLK = W * TPB;              // 1024
constexpr int CHUNKS      = 6;                    // 6*1024 = 6144 >= 6141
constexpr long long TOTAL_IN = (long long)B_SZ * FLT_PER_ROW;  // 18,874,368
}

__device__ __forceinline__ void dihedral_core(
    float e0x, float e0y, float e0z,
    float e1x, float e1y, float e1z,
    float e2x, float e2y, float e2z,
    float& sv, float& cv)
{
    // u = normalize(e1 + 1e-8)
    const float ux0 = e1x + 1e-8f;
    const float uy0 = e1y + 1e-8f;
    const float uz0 = e1z + 1e-8f;
    const float rin = rsqrtf(fmaf(ux0, ux0, fmaf(uy0, uy0, uz0 * uz0)));
    const float ux = ux0 * rin, uy = uy0 * rin, uz = uz0 * rin;

    // n1 = cross(e0, u)
    const float n1x = fmaf(e0y, uz, -e0z * uy);
    const float n1y = fmaf(e0z, ux, -e0x * uz);
    const float n1z = fmaf(e0x, uy, -e0y * ux);
    // n2 = cross(u, e2)
    const float n2x = fmaf(uy, e2z, -uz * e2y);
    const float n2y = fmaf(uz, e2x, -ux * e2z);
    const float n2z = fmaf(ux, e2y, -uy * e2x);

    // xc = n1.n2 + 1e-8 ; yc = (n1 x u).n2 == -e0.n2  (u.n2 == 0, |u| = 1)
    const float xc = fmaf(n1x, n2x, fmaf(n1y, n2y, fmaf(n1z, n2z, 1e-8f)));
    const float yc = -fmaf(e0x, n2x, fmaf(e0y, n2y, e0z * n2z));

    const float r2 = fmaf(xc, xc, yc * yc);
    const float ri = rsqrtf(r2);
    sv = (r2 > 0.0f) ? yc * ri : 0.0f;   // atan2(0,0)=0
    cv = (r2 > 0.0f) ? xc * ri : 1.0f;
}

__global__ __launch_bounds__(TPB)
void dihedral_kernel(const float* __restrict__ in, float* __restrict__ out) {
    const int bid   = blockIdx.x;
    const int batch = bid / CHUNKS;
    const int chunk = bid - batch * CHUNKS;
    const int lane  = threadIdx.x & 31;
    const int gw0   = chunk * WIN_PER_BLK + threadIdx.x * W;

    const long long rowBase = (long long)batch * FLT_PER_ROW;
    const long long fbase   = rowBase + (long long)gw0 * 3;   // multiple of 12 -> 16B aligned

    // ── Owned floats f[0..11]: 3 aligned LDG.128 (48B lane stride). Always in bounds.
    float f[12];
    {
        const float4* p4p = reinterpret_cast<const float4*>(in + fbase);
        const float4 v0 = p4p[0], v1 = p4p[1], v2 = p4p[2];
        f[0]=v0.x; f[1]=v0.y; f[2]=v0.z;  f[3]=v0.w;
        f[4]=v1.x; f[5]=v1.y; f[6]=v1.z;  f[7]=v1.w;
        f[8]=v2.x; f[9]=v2.y; f[10]=v2.z; f[11]=v2.w;
    }

    // ── Hoisted predicated overlap loads (lane 31 only): maximize per-warp MLP.
    float g[9];
    const bool last = (lane == 31);
    if (last) {
        const long long gbase = fbase + 12;             // 16B aligned
        if (gbase + 9 <= TOTAL_IN) {                    // false only for the global tail thread
            const float4 v0 = *reinterpret_cast<const float4*>(in + gbase);
            const float4 v1 = *reinterpret_cast<const float4*>(in + gbase + 4);
            g[0]=v0.x; g[1]=v0.y; g[2]=v0.z; g[3]=v0.w;
            g[4]=v1.x; g[5]=v1.y; g[6]=v1.z; g[7]=v1.w;
            g[8] = in[gbase + 8];
        } else {
            #pragma unroll
            for (int j = 0; j < 9; j++)
                g[j] = (gbase + j < TOTAL_IN) ? in[gbase + j] : 0.0f;
        }
    }

    // ── Owned edges E_j = p_j - p_{j+1}, j = 0..2 (from f only).
    const float E0x = f[0]-f[3],  E0y = f[1]-f[4],  E0z = f[2]-f[5];
    const float E1x = f[3]-f[6],  E1y = f[4]-f[7],  E1z = f[5]-f[8];
    const float E2x = f[6]-f[9],  E2y = f[7]-f[10], E2z = f[8]-f[11];

    // ── Neighbor data via shuffle: p4 = next thread's p0; E4 = E0'; E5 = E1'.
    float p4x = __shfl_down_sync(0xFFFFFFFFu, f[0], 1);
    float p4y = __shfl_down_sync(0xFFFFFFFFu, f[1], 1);
    float p4z = __shfl_down_sync(0xFFFFFFFFu, f[2], 1);
    float E4x = __shfl_down_sync(0xFFFFFFFFu, E0x, 1);
    float E4y = __shfl_down_sync(0xFFFFFFFFu, E0y, 1);
    float E4z = __shfl_down_sync(0xFFFFFFFFu, E0z, 1);
    float E5x = __shfl_down_sync(0xFFFFFFFFu, E1x, 1);
    float E5y = __shfl_down_sync(0xFFFFFFFFu, E1y, 1);
    float E5z = __shfl_down_sync(0xFFFFFFFFu, E1z, 1);
    if (last) {                                          // warp boundary: use direct loads
        p4x = g[0]; p4y = g[1]; p4z = g[2];
        E4x = g[0]-g[3]; E4y = g[1]-g[4]; E4z = g[2]-g[5];
        E5x = g[3]-g[6]; E5y = g[4]-g[7]; E5z = g[5]-g[8];
    }
    // Boundary edge E3 = p3 - p4.
    const float E3x = f[9]-p4x, E3y = f[10]-p4y, E3z = f[11]-p4z;

    float sv[W], cv[W];
    dihedral_core(E0x,E0y,E0z, E1x,E1y,E1z, E2x,E2y,E2z, sv[0], cv[0]);
    dihedral_core(E1x,E1y,E1z, E2x,E2y,E2z, E3x,E3y,E3z, sv[1], cv[1]);
    dihedral_core(E2x,E2y,E2z, E3x,E3y,E3z, E4x,E4y,E4z, sv[2], cv[2]);
    dihedral_core(E3x,E3y,E3z, E4x,E4y,E4z, E5x,E5y,E5z, sv[3], cv[3]);

    const long long ob = (long long)batch * OUT_STRIDE;

    if (gw0 + W <= NWIN) {
        // sin: (ob+gw0) even -> 8B-aligned float2 streaming stores
        float2* s2 = reinterpret_cast<float2*>(out + ob + gw0);
        __stcs(s2 + 0, make_float2(sv[0], sv[1]));
        __stcs(s2 + 1, make_float2(sv[2], sv[3]));
        // cos: offset NWIN (odd) -> streaming scalar stores
        float* cp = out + ob + NWIN + gw0;
        __stcs(cp + 0, cv[0]); __stcs(cp + 1, cv[1]);
        __stcs(cp + 2, cv[2]); __stcs(cp + 3, cv[3]);
    } else {
        #pragma unroll
        for (int w = 0; w < W; w++) {
            if (gw0 + w < NWIN) {
                __stcs(out + ob + gw0 + w,        sv[w]);
                __stcs(out + ob + NWIN + gw0 + w, cv[w]);
            }
        }
    }

    // first_three: 9 floats per batch appended after all angle rows.
    if (chunk == 0 && threadIdx.x < 9) {
        out[(long long)B_SZ * OUT_STRIDE + (long long)batch * 9 + threadIdx.x] =
            in[rowBase + threadIdx.x];
    }
}

extern "C" void kernel_launch(void* const* d_in, const int* in_sizes, int n_in,
                              void* d_out, int out_size) {
    const float* in = (const float*)d_in[0];
    float* out = (float*)d_out;
    dihedral_kernel<<<B_SZ * CHUNKS, TPB>>>(in, out);
}